// round 8
// baseline (speedup 1.0000x reference)
#include <cuda_runtime.h>

#define NUM_CLS   8
#define MAX_INST  64
#define NB        32            // batch
#define HW        (1024*1024)   // pixels per sample
#define HT        256           // threads per block
#define CHUNKS    32            // blocks per sample along pixel dim
#define GRID      (NB * CHUNKS) // 1024 blocks ~= one wave at 7 blocks/SM

__device__ __align__(16) int g_inst_sizes[NB * MAX_INST];  // static-zero; reset each run
__device__ unsigned int g_done;                            // static-zero; reset each run

// One fused kernel: per-block 64-bin histogram (privatized u16 counters),
// global accumulation via atomics, last-block-done computes the BCE loss.
__global__ __launch_bounds__(HT, 7) void fused_kernel(const int*   __restrict__ mask,
                                                      const float* __restrict__ pred,
                                                      const int*   __restrict__ label_raw,
                                                      float*       __restrict__ out) {
    __shared__ __align__(16) unsigned short cnt[MAX_INST * HT];  // 32 KB, reused in tail
    __shared__ unsigned int s_ticket;

    const int tid = threadIdx.x;
    unsigned int* cnt32 = (unsigned int*)cnt;

    #pragma unroll
    for (int i = tid; i < MAX_INST * HT / 2; i += HT) cnt32[i] = 0u;
    __syncthreads();

    const int sample = blockIdx.y;
    const int chunk  = blockIdx.x;
    const int elems  = HW / CHUNKS;     // 32768 per block

    const int4* __restrict__ p =
        (const int4*)(mask + (size_t)sample * HW + (size_t)chunk * elems) + tid;

    // Swizzled private-counter slot: column = bin, slot = (tid + 2*bin) & 255.
    // u16 bank = (tid/2 + bin) % 32 -> lane pairs conflict only when bins are
    // congruent mod 32 (p=1/32), vs a guaranteed 2-way conflict unswizzled.
#define INC(v) { int _b = (v) & 63; cnt[(_b << 8) + ((tid + 2 * _b) & 255)]++; }

    // 32 int4/thread: 8 iters of 4 explicitly-batched independent loads (MLP=4,
    // 16 load regs -> occupancy stays smem-limited at 7 blocks/SM).
    #pragma unroll 2
    for (int it = 0; it < 8; it++) {
        int4 a = p[0 * HT];
        int4 b = p[1 * HT];
        int4 c = p[2 * HT];
        int4 d = p[3 * HT];
        p += 4 * HT;
        INC(a.x); INC(a.y); INC(a.z); INC(a.w);
        INC(b.x); INC(b.y); INC(b.z); INC(b.w);
        INC(c.x); INC(c.y); INC(c.z); INC(c.w);
        INC(d.x); INC(d.y); INC(d.z); INC(d.w);
    }
#undef INC
    __syncthreads();

    // Reduce 256 u16 lanes per bin (swizzle is a permutation within the column,
    // so a full-column sum is unchanged): 4 threads/bin, tid-staggered.
    unsigned int s = 0;
    {
        const int b = tid & 63;
        const int j = tid >> 6;
        #pragma unroll
        for (int i = 0; i < 32; i++) {
            unsigned int w = cnt32[b * (HT / 2) + j * 32 + ((i + tid) & 31)];
            s += (w & 0xffffu) + (w >> 16);
        }
    }
    __syncthreads();
    unsigned int* psum = cnt32;           // reuse smem
    psum[tid] = s;
    __syncthreads();
    if (tid < MAX_INST) {
        unsigned int t = psum[tid] + psum[tid + 64] + psum[tid + 128] + psum[tid + 192];
        atomicAdd(&g_inst_sizes[sample * MAX_INST + tid], (int)t);
    }

    // ---- last-block-done handoff ----
    __threadfence();                       // bin atomics visible before ticket
    __syncthreads();
    if (tid == 0) s_ticket = atomicAdd(&g_done, 1u);
    __syncthreads();
    if (s_ticket != GRID - 1) return;      // uniform exit for non-last blocks

    // ================= last block: loss computation =================
    __threadfence();                       // acquire: see all blocks' bin atomics

    int*   isz   = (int*)cnt32;            // [2048] totals (8 KB)
    int*   cnts  = isz + NB * MAX_INST;    // [256] per-class pixel counts
    float* red   = (float*)(cnts + NB * NUM_CLS);
    int*   flags = (int*)(red + 8);

    for (int i = tid; i < NB * MAX_INST / 4; i += HT)
        ((int4*)isz)[i] = ((const int4*)g_inst_sizes)[i];     // L2-hot, 8 KB
    if (tid == 0) flags[0] = 0;
    if (tid < NB * NUM_CLS) cnts[tid] = 0;
    __syncthreads();

    // Reset globals for the next graph replay (after totals are in shared).
    for (int i = tid; i < NB * MAX_INST / 4; i += HT)
        ((int4*)g_inst_sizes)[i] = make_int4(0, 0, 0, 0);
    if (tid == 0) g_done = 0u;

    // int64-vs-int32 layout detection: values < 32, so little-endian int64
    // means every odd 32-bit word of the first 64 values is 0.
    if (tid < 64) {
        if (label_raw[2 * tid + 1] != 0) atomicOr(&flags[0], 1);
    }
    __syncthreads();

    const int is64 = !flags[0];
    for (int q = tid; q < NB * 64; q += HT) {
        int b = q >> 6;
        int id, lbl;
        if (is64) { id = label_raw[4 * q]; lbl = label_raw[4 * q + 2]; }
        else      { id = label_raw[2 * q]; lbl = label_raw[2 * q + 1]; }
        if (lbl > 0 && lbl <= NUM_CLS)
            atomicAdd(&cnts[b * NUM_CLS + lbl - 1], isz[b * MAX_INST + (id & (MAX_INST - 1))]);
    }
    __syncthreads();

    float term = 0.0f;
    if (tid < NB * NUM_CLS) {
        float x  = pred[tid];
        float cl = fminf((float)cnts[tid] * (1.0f / 100.0f), 1.0f);
        term = fmaxf(x, 0.0f) - x * cl + log1pf(expf(-fabsf(x)));
    }
    #pragma unroll
    for (int o = 16; o; o >>= 1) term += __shfl_down_sync(0xffffffffu, term, o);
    if ((tid & 31) == 0) red[tid >> 5] = term;
    __syncthreads();
    if (tid < 8) {
        float sr = red[tid];
        #pragma unroll
        for (int o = 4; o; o >>= 1) sr += __shfl_down_sync(0xffu, sr, o);
        if (tid == 0) out[0] = sr * (1.0f / (float)(NB * NUM_CLS));
    }
}

// ---------------- launch ----------------
extern "C" void kernel_launch(void* const* d_in, const int* in_sizes, int n_in,
                              void* d_out, int out_size) {
    const float* pred  = (const float*)d_in[0];          // [32, 8] f32
    const int*   mask  = (const int*)d_in[1];            // [32, 1024, 1024] i32
    const int*   label = (const int*)d_in[2];            // [32, 64, 2] i32 or i64
    float*       out   = (float*)d_out;

    dim3 grid(CHUNKS, NB);
    fused_kernel<<<grid, HT>>>(mask, pred, label, out);
}

// round 10
// speedup vs baseline: 1.2084x; 1.2084x over previous
#include <cuda_runtime.h>

#define NUM_CLS   8
#define MAX_INST  64
#define NB        32            // batch
#define HW        (1024*1024)   // pixels per sample
#define HT        256           // threads per block
#define CHUNKS    32            // blocks per sample along pixel dim
#define GRID      (NB * CHUNKS)

__device__ __align__(16) int g_inst_sizes[NB * MAX_INST];  // static-zero; reset each run
__device__ unsigned int g_done;                            // static-zero; reset each run

// Fused kernel: per-block 64-bin histogram with CONFLICT-FREE split-u32
// private counters (word w = bin&31 holds bins w / w+32 in its u16 halves;
// bank = tid%32 independent of data), then last-block-done computes the loss.
__global__ __launch_bounds__(HT) void fused_kernel(const int*   __restrict__ mask,
                                                   const float* __restrict__ pred,
                                                   const int*   __restrict__ label_raw,
                                                   float*       __restrict__ out) {
    __shared__ __align__(16) unsigned int cnt32[32 * HT];   // 32 KB, reused in tail
    __shared__ int binsum[MAX_INST];
    __shared__ unsigned int s_ticket;

    const int tid = threadIdx.x;

    #pragma unroll
    for (int i = tid; i < 32 * HT; i += HT) cnt32[i] = 0u;
    if (tid < MAX_INST) binsum[tid] = 0;
    __syncthreads();

    const int sample = blockIdx.y;
    const int chunk  = blockIdx.x;
    const int elems  = HW / CHUNKS;     // 32768 per block

    const int4* __restrict__ p =
        (const int4*)(mask + (size_t)sample * HW + (size_t)chunk * elems) + tid;

    // bank = tid%32 always: no conflicts for any bin pattern.
#define INC(v) { unsigned int _w = (unsigned int)(v) & 31u;                    \
                 unsigned int _i = 1u << (((unsigned int)(v) & 32u) >> 1);     \
                 cnt32[(_w << 8) + tid] += _i; }

    // 32 int4/thread: 8 iters of 4 explicitly-batched independent loads (MLP=4).
    #pragma unroll 2
    for (int it = 0; it < 8; it++) {
        int4 a = p[0 * HT];
        int4 b = p[1 * HT];
        int4 c = p[2 * HT];
        int4 d = p[3 * HT];
        p += 4 * HT;
        INC(a.x); INC(a.y); INC(a.z); INC(a.w);
        INC(b.x); INC(b.y); INC(b.z); INC(b.w);
        INC(c.x); INC(c.y); INC(c.z); INC(c.w);
        INC(d.x); INC(d.y); INC(d.z); INC(d.w);
    }
#undef INC
    __syncthreads();

    // Reduce: word column w has 256 thread slots; 8 threads per column
    // (j = tid>>5), each sums 32 staggered slots -> conflict-free LDS.
    {
        const int w = tid & 31;
        const int j = tid >> 5;
        unsigned int s_lo = 0, s_hi = 0;
        #pragma unroll
        for (int i = 0; i < 32; i++) {
            unsigned int v = cnt32[(w << 8) + j * 32 + ((i + tid) & 31)];
            s_lo += v & 0xffffu;
            s_hi += v >> 16;
        }
        atomicAdd(&binsum[w],      (int)s_lo);   // bin w
        atomicAdd(&binsum[w + 32], (int)s_hi);   // bin w+32
    }
    __syncthreads();
    if (tid < MAX_INST)
        atomicAdd(&g_inst_sizes[sample * MAX_INST + tid], binsum[tid]);

    // ---- last-block-done handoff ----
    __threadfence();
    __syncthreads();
    if (tid == 0) s_ticket = atomicAdd(&g_done, 1u);
    __syncthreads();
    if (s_ticket != GRID - 1) return;

    // ================= last block: loss computation =================
    __threadfence();                       // acquire: see all blocks' bin atomics

    int*   isz   = (int*)cnt32;            // [2048] totals (8 KB)
    int*   cnts  = isz + NB * MAX_INST;    // [256] per-class pixel counts
    float* red   = (float*)(cnts + NB * NUM_CLS);
    int*   flags = (int*)(red + 8);

    for (int i = tid; i < NB * MAX_INST / 4; i += HT)
        ((int4*)isz)[i] = ((const int4*)g_inst_sizes)[i];     // L2-hot, 8 KB
    if (tid == 0) flags[0] = 0;
    if (tid < NB * NUM_CLS) cnts[tid] = 0;
    __syncthreads();

    // Reset globals for the next graph replay.
    for (int i = tid; i < NB * MAX_INST / 4; i += HT)
        ((int4*)g_inst_sizes)[i] = make_int4(0, 0, 0, 0);
    if (tid == 0) g_done = 0u;

    // int64-vs-int32 layout detection: values < 32, so little-endian int64
    // means every odd 32-bit word of the first 64 values is 0.
    if (tid < 64) {
        if (label_raw[2 * tid + 1] != 0) atomicOr(&flags[0], 1);
    }
    __syncthreads();

    const int is64 = !flags[0];
    for (int q = tid; q < NB * 64; q += HT) {
        int b = q >> 6;
        int id, lbl;
        if (is64) { id = label_raw[4 * q]; lbl = label_raw[4 * q + 2]; }
        else      { id = label_raw[2 * q]; lbl = label_raw[2 * q + 1]; }
        if (lbl > 0 && lbl <= NUM_CLS)
            atomicAdd(&cnts[b * NUM_CLS + lbl - 1], isz[b * MAX_INST + (id & (MAX_INST - 1))]);
    }
    __syncthreads();

    float term = 0.0f;
    if (tid < NB * NUM_CLS) {
        float x  = pred[tid];
        float cl = fminf((float)cnts[tid] * (1.0f / 100.0f), 1.0f);
        term = fmaxf(x, 0.0f) - x * cl + log1pf(expf(-fabsf(x)));
    }
    #pragma unroll
    for (int o = 16; o; o >>= 1) term += __shfl_down_sync(0xffffffffu, term, o);
    if ((tid & 31) == 0) red[tid >> 5] = term;
    __syncthreads();
    if (tid < 8) {
        float sr = red[tid];
        #pragma unroll
        for (int o = 4; o; o >>= 1) sr += __shfl_down_sync(0xffu, sr, o);
        if (tid == 0) out[0] = sr * (1.0f / (float)(NB * NUM_CLS));
    }
}

// ---------------- launch ----------------
extern "C" void kernel_launch(void* const* d_in, const int* in_sizes, int n_in,
                              void* d_out, int out_size) {
    const float* pred  = (const float*)d_in[0];          // [32, 8] f32
    const int*   mask  = (const int*)d_in[1];            // [32, 1024, 1024] i32
    const int*   label = (const int*)d_in[2];            // [32, 64, 2] i32 or i64
    float*       out   = (float*)d_out;

    dim3 grid(CHUNKS, NB);
    fused_kernel<<<grid, HT>>>(mask, pred, label, out);
}

// round 11
// speedup vs baseline: 1.5029x; 1.2437x over previous
#include <cuda_runtime.h>

#define NUM_CLS   8
#define MAX_INST  64
#define NB        32            // batch
#define HW        (1024*1024)   // pixels per sample
#define HT        256           // threads per block
#define CHUNKS    32            // blocks per sample along pixel dim
#define GRID      (NB * CHUNKS)

__device__ __align__(16) int g_inst_sizes[NB * MAX_INST];  // static-zero; reset each run
__device__ unsigned int g_done;                            // static-zero; reset each run

// Fused kernel: per-block 64-bin histogram with CONFLICT-FREE packed-u8
// private counters (word w = bin&15 holds bins w, w+16, w+32, w+48 in its
// bytes; bank = tid%32 independent of data; max 128 elems/thread -> u8 safe).
// 16 KB smem + reg cap 32 -> 8 blocks/SM = 64 warps for DRAM latency hiding.
__global__ __launch_bounds__(HT, 8) void fused_kernel(const int*   __restrict__ mask,
                                                      const float* __restrict__ pred,
                                                      const int*   __restrict__ label_raw,
                                                      float*       __restrict__ out) {
    __shared__ __align__(16) unsigned int cnt32[16 * HT];   // 16 KB, reused in tail
    __shared__ int binsum[MAX_INST];
    __shared__ unsigned int s_ticket;

    const int tid = threadIdx.x;

    #pragma unroll
    for (int i = tid; i < 16 * HT; i += HT) cnt32[i] = 0u;
    if (tid < MAX_INST) binsum[tid] = 0;
    __syncthreads();

    const int sample = blockIdx.y;
    const int chunk  = blockIdx.x;
    const int elems  = HW / CHUNKS;     // 32768 per block

    const int4* __restrict__ p =
        (const int4*)(mask + (size_t)sample * HW + (size_t)chunk * elems) + tid;

    // bank = tid%32 always: no conflicts for any bin pattern.
#define INC(v) { unsigned int _u = (unsigned int)(v);                          \
                 cnt32[((_u & 15u) << 8) + tid] += 1u << ((_u & 48u) >> 1); }

    // 32 int4/thread: 8 iters of 4 explicitly-batched independent loads.
    #pragma unroll 2
    for (int it = 0; it < 8; it++) {
        int4 a = p[0 * HT];
        int4 b = p[1 * HT];
        int4 c = p[2 * HT];
        int4 d = p[3 * HT];
        p += 4 * HT;
        INC(a.x); INC(a.y); INC(a.z); INC(a.w);
        INC(b.x); INC(b.y); INC(b.z); INC(b.w);
        INC(c.x); INC(c.y); INC(c.z); INC(c.w);
        INC(d.x); INC(d.y); INC(d.z); INC(d.w);
    }
#undef INC
    __syncthreads();

    // Reduce: word column w (16 cols x 256 slots); 16 threads per column
    // (j = tid>>4), each sums 16 staggered slots -> conflict-free LDS.
    // Packed pair accumulators: sA holds bins w (lo16) / w+32 (hi16),
    // sB holds w+16 / w+48. Max per half = 16*128 < 65536, no overflow.
    {
        const int w = tid & 15;
        const int j = tid >> 4;
        unsigned int sA = 0, sB = 0;
        #pragma unroll
        for (int i = 0; i < 16; i++) {
            unsigned int v = cnt32[(w << 8) + j * 16 + ((i + tid) & 15)];
            sA += v & 0x00FF00FFu;
            sB += (v >> 8) & 0x00FF00FFu;
        }
        atomicAdd(&binsum[w],      (int)(sA & 0xFFFFu));
        atomicAdd(&binsum[w + 16], (int)(sB & 0xFFFFu));
        atomicAdd(&binsum[w + 32], (int)(sA >> 16));
        atomicAdd(&binsum[w + 48], (int)(sB >> 16));
    }
    __syncthreads();
    if (tid < MAX_INST)
        atomicAdd(&g_inst_sizes[sample * MAX_INST + tid], binsum[tid]);

    // ---- last-block-done handoff ----
    __threadfence();
    __syncthreads();
    if (tid == 0) s_ticket = atomicAdd(&g_done, 1u);
    __syncthreads();
    if (s_ticket != GRID - 1) return;

    // ================= last block: loss computation =================
    __threadfence();                       // acquire: see all blocks' bin atomics

    int*   isz   = (int*)cnt32;            // [2048] totals (8 KB, fits in 16 KB)
    int*   cnts  = isz + NB * MAX_INST;    // [256] per-class pixel counts
    float* red   = (float*)(cnts + NB * NUM_CLS);
    int*   flags = (int*)(red + 8);

    for (int i = tid; i < NB * MAX_INST / 4; i += HT)
        ((int4*)isz)[i] = ((const int4*)g_inst_sizes)[i];     // L2-hot, 8 KB
    if (tid == 0) flags[0] = 0;
    if (tid < NB * NUM_CLS) cnts[tid] = 0;
    __syncthreads();

    // Reset globals for the next graph replay.
    for (int i = tid; i < NB * MAX_INST / 4; i += HT)
        ((int4*)g_inst_sizes)[i] = make_int4(0, 0, 0, 0);
    if (tid == 0) g_done = 0u;

    // int64-vs-int32 layout detection: values < 32, so little-endian int64
    // means every odd 32-bit word of the first 64 values is 0.
    if (tid < 64) {
        if (label_raw[2 * tid + 1] != 0) atomicOr(&flags[0], 1);
    }
    __syncthreads();

    const int is64 = !flags[0];
    for (int q = tid; q < NB * 64; q += HT) {
        int b = q >> 6;
        int id, lbl;
        if (is64) { id = label_raw[4 * q]; lbl = label_raw[4 * q + 2]; }
        else      { id = label_raw[2 * q]; lbl = label_raw[2 * q + 1]; }
        if (lbl > 0 && lbl <= NUM_CLS)
            atomicAdd(&cnts[b * NUM_CLS + lbl - 1], isz[b * MAX_INST + (id & (MAX_INST - 1))]);
    }
    __syncthreads();

    float term = 0.0f;
    if (tid < NB * NUM_CLS) {
        float x  = pred[tid];
        float cl = fminf((float)cnts[tid] * (1.0f / 100.0f), 1.0f);
        term = fmaxf(x, 0.0f) - x * cl + log1pf(expf(-fabsf(x)));
    }
    #pragma unroll
    for (int o = 16; o; o >>= 1) term += __shfl_down_sync(0xffffffffu, term, o);
    if ((tid & 31) == 0) red[tid >> 5] = term;
    __syncthreads();
    if (tid < 8) {
        float sr = red[tid];
        #pragma unroll
        for (int o = 4; o; o >>= 1) sr += __shfl_down_sync(0xffu, sr, o);
        if (tid == 0) out[0] = sr * (1.0f / (float)(NB * NUM_CLS));
    }
}

// ---------------- launch ----------------
extern "C" void kernel_launch(void* const* d_in, const int* in_sizes, int n_in,
                              void* d_out, int out_size) {
    const float* pred  = (const float*)d_in[0];          // [32, 8] f32
    const int*   mask  = (const int*)d_in[1];            // [32, 1024, 1024] i32
    const int*   label = (const int*)d_in[2];            // [32, 64, 2] i32 or i64
    float*       out   = (float*)d_out;

    dim3 grid(CHUNKS, NB);
    fused_kernel<<<grid, HT>>>(mask, pred, label, out);
}